// round 1
// baseline (speedup 1.0000x reference)
#include <cuda_runtime.h>
#include <cstdint>
#include <math.h>

#define B_ 2
#define T_ 2048
#define C_ 4096
#define H_ 32
#define D_ 128
#define M_ (B_*T_)   /* 4096 rows */
#define K_ C_
#define N_ C_

// Scratch (device globals: allocation-guard safe)
__device__ float g_q[(size_t)B_*H_*T_*D_];
__device__ float g_k[(size_t)B_*H_*T_*D_];
__device__ float g_v[(size_t)B_*H_*T_*D_];
__device__ float g_att[(size_t)M_*C_];
__device__ float g_rope[T_*64];

// ---------------------------------------------------------------------------
// RoPE table: reference's rotate_half is identity, so scale = cos(m)+sin(m),
// m[t][j] = t * 10000^(-2j/128), j = d % 64.
// ---------------------------------------------------------------------------
__global__ void rope_kernel() {
    int i = blockIdx.x * blockDim.x + threadIdx.x;
    if (i >= T_ * 64) return;
    int t = i >> 6, j = i & 63;
    float ex = (float)(2 * j) * (1.0f / 128.0f);
    float f  = 1.0f / powf(10000.0f, ex);
    float m  = (float)t * f;
    g_rope[i] = cosf(m) + sinf(m);
}

// ---------------------------------------------------------------------------
// tf32 helpers
// ---------------------------------------------------------------------------
__device__ __forceinline__ uint32_t f2tf(float x) {
    uint32_t u;
    asm("cvt.rna.tf32.f32 %0, %1;" : "=r"(u) : "f"(x));
    return u;
}

__device__ __forceinline__ void mma8(float* d, const uint32_t* a, const uint32_t* b) {
    asm volatile(
        "mma.sync.aligned.m16n8k8.row.col.f32.tf32.tf32.f32 "
        "{%0,%1,%2,%3}, {%4,%5,%6,%7}, {%8,%9}, {%0,%1,%2,%3};\n"
        : "+f"(d[0]), "+f"(d[1]), "+f"(d[2]), "+f"(d[3])
        : "r"(a[0]), "r"(a[1]), "r"(a[2]), "r"(a[3]), "r"(b[0]), "r"(b[1]));
}

// ---------------------------------------------------------------------------
// tf32 GEMM: C[4096,4096] = A[4096,4096] @ W[4096,4096] (both row-major).
// MODE 0: A = X input, gridDim.z selects Wq/Wk/Wv; epilogue applies RoPE
//         (z<2) and writes to g_q/g_k/g_v in [b,h,t,d] layout.
// MODE 1: A = g_att (attention output, [b*t, h*d]); plain write to Cout.
// Block tile 128x128x32, 8 warps (2x4), warp tile 64x32, m16n8k8 frags.
// ---------------------------------------------------------------------------
#define BM 128
#define BN 128
#define BK 32
#define AS_STRIDE 36    /* pad so A-frag LDS is conflict-free */
#define BS_STRIDE 136   /* pad so B-frag LDS is conflict-free */

template<int MODE>
__global__ void __launch_bounds__(256, 1) gemm_tf32(
    const float* __restrict__ Ain, const float* __restrict__ W0,
    const float* __restrict__ W1,  const float* __restrict__ W2,
    float* __restrict__ Cout)
{
    __shared__ uint32_t As[BM][AS_STRIDE];
    __shared__ uint32_t Bs[BK][BS_STRIDE];

    const float* A = (MODE == 0) ? Ain : g_att;
    const float* Bm = W0;
    int z = 0;
    if (MODE == 0) {
        z = blockIdx.z;
        Bm = (z == 0) ? W0 : (z == 1) ? W1 : W2;
    }

    const int tid = threadIdx.x;
    const int m0 = blockIdx.x * BM;
    const int n0 = blockIdx.y * BN;

    // Global staging indices: A tile 128x32 (4 float4/thread), B tile 32x128.
    const int arow = tid >> 3;          // 0..31 (+ r*32)
    const int acol = (tid & 7) * 4;     // col within BK
    const int brow = tid >> 5;          // 0..7  (+ r*8)
    const int bcol = (tid & 31) * 4;    // col within BN

    const float* Abase = A  + (size_t)(m0 + arow) * K_ + acol;
    const float* Bbase = Bm + (size_t)brow * N_ + n0 + bcol;

    uint4 ast[4], bst[4];
    auto gload = [&](int kt) {
        #pragma unroll
        for (int r = 0; r < 4; r++) {
            float4 v = *(const float4*)(Abase + (size_t)(r * 32) * K_ + kt * BK);
            ast[r] = make_uint4(f2tf(v.x), f2tf(v.y), f2tf(v.z), f2tf(v.w));
        }
        #pragma unroll
        for (int r = 0; r < 4; r++) {
            float4 v = *(const float4*)(Bbase + (size_t)(kt * BK + r * 8) * N_);
            bst[r] = make_uint4(f2tf(v.x), f2tf(v.y), f2tf(v.z), f2tf(v.w));
        }
    };
    auto sstore = [&]() {
        #pragma unroll
        for (int r = 0; r < 4; r++)
            *(uint4*)&As[arow + r * 32][acol] = ast[r];
        #pragma unroll
        for (int r = 0; r < 4; r++)
            *(uint4*)&Bs[brow + r * 8][bcol] = bst[r];
    };

    const int wid = tid >> 5, lane = tid & 31;
    const int wm = (wid >> 2) * 64;     // warp m-offset (0/64)
    const int wn = (wid & 3) * 32;      // warp n-offset
    const int lr = lane >> 2, lc = lane & 3;

    float acc[4][4][4];
    #pragma unroll
    for (int i = 0; i < 4; i++)
        #pragma unroll
        for (int j = 0; j < 4; j++)
            #pragma unroll
            for (int k = 0; k < 4; k++) acc[i][j][k] = 0.f;

    const int NT = K_ / BK;
    gload(0);
    sstore();
    for (int kt = 0; kt < NT; kt++) {
        __syncthreads();
        if (kt + 1 < NT) gload(kt + 1);  // overlap next-tile GMEM with compute
        #pragma unroll
        for (int kk = 0; kk < BK; kk += 8) {
            uint32_t af[4][4];
            #pragma unroll
            for (int mi = 0; mi < 4; mi++) {
                int r0 = wm + mi * 16 + lr;
                af[mi][0] = As[r0][kk + lc];
                af[mi][1] = As[r0 + 8][kk + lc];
                af[mi][2] = As[r0][kk + lc + 4];
                af[mi][3] = As[r0 + 8][kk + lc + 4];
            }
            uint32_t bf[4][2];
            #pragma unroll
            for (int ni = 0; ni < 4; ni++) {
                int c0 = wn + ni * 8 + lr;
                bf[ni][0] = Bs[kk + lc][c0];
                bf[ni][1] = Bs[kk + lc + 4][c0];
            }
            #pragma unroll
            for (int mi = 0; mi < 4; mi++)
                #pragma unroll
                for (int ni = 0; ni < 4; ni++)
                    mma8(acc[mi][ni], af[mi], bf[ni]);
        }
        __syncthreads();
        if (kt + 1 < NT) sstore();
    }

    // Epilogue
    #pragma unroll
    for (int mi = 0; mi < 4; mi++) {
        #pragma unroll
        for (int ni = 0; ni < 4; ni++) {
            #pragma unroll
            for (int idx = 0; idx < 4; idx++) {
                int row = m0 + wm + mi * 16 + lr + ((idx >> 1) * 8);
                int col = n0 + wn + ni * 8 + lc * 2 + (idx & 1);
                float v = acc[mi][ni][idx];
                if (MODE == 0) {
                    int b = row >> 11, t = row & (T_ - 1);
                    int h = col >> 7,  d = col & (D_ - 1);
                    if (z < 2) v *= g_rope[t * 64 + (d & 63)];
                    float* dst = (z == 0) ? g_q : (z == 1) ? g_k : g_v;
                    dst[(size_t)((b * H_ + h) * T_ + t) * D_ + d] = v;
                } else {
                    Cout[(size_t)row * N_ + col] = v;
                }
            }
        }
    }
}

// ---------------------------------------------------------------------------
// fp32 SIMT flash attention (causal). CTA = 128 thr = 16 q-rows x 8 thr/row.
// Key tiles of 32 (K,V staged in smem), online softmax, causal tile skip.
// Writes output directly in [b, t, h*D+d] layout (row-major 4096x4096) so
// the final projection GEMM consumes it as plain row-major A.
// ---------------------------------------------------------------------------
__global__ void __launch_bounds__(128) attn_kernel() {
    __shared__ float Ks[32 * 128];
    __shared__ float Vs[32 * 128];

    const int bh = blockIdx.y;              // b*H + h
    const int qbase = blockIdx.x * 16;
    const int tid = threadIdx.x;
    const int rowi = tid >> 3;              // 0..15
    const int l8 = tid & 7;                 // lane within row-group
    const int gq = qbase + rowi;

    const float* qp = g_q + ((size_t)bh * T_ + gq) * D_ + l8 * 16;
    float q_r[16], o_r[16];
    #pragma unroll
    for (int i = 0; i < 16; i += 4) {
        float4 v = *(const float4*)(qp + i);
        q_r[i] = v.x; q_r[i+1] = v.y; q_r[i+2] = v.z; q_r[i+3] = v.w;
    }
    #pragma unroll
    for (int i = 0; i < 16; i++) o_r[i] = 0.f;

    float mrun = -INFINITY, lrun = 0.f;
    const int ntiles = (qbase + 15) / 32 + 1;   // causal upper bound for block

    const float4* Kg = (const float4*)(g_k + (size_t)bh * T_ * D_);
    const float4* Vg = (const float4*)(g_v + (size_t)bh * T_ * D_);
    float4* Ks4 = (float4*)Ks;
    float4* Vs4 = (float4*)Vs;

    for (int kt = 0; kt < ntiles; kt++) {
        const int kb = kt * 32;
        __syncthreads();
        #pragma unroll
        for (int i = 0; i < 8; i++) {
            Ks4[tid + i * 128] = Kg[kb * 32 + tid + i * 128];
            Vs4[tid + i * 128] = Vg[kb * 32 + tid + i * 128];
        }
        __syncthreads();

        float s[32];
        #pragma unroll
        for (int j = 0; j < 32; j++) {
            const float* kr = Ks + j * 128 + l8 * 16;
            float a = 0.f;
            #pragma unroll
            for (int i = 0; i < 16; i++) a = fmaf(q_r[i], kr[i], a);
            a += __shfl_xor_sync(0xffffffffu, a, 1);
            a += __shfl_xor_sync(0xffffffffu, a, 2);
            a += __shfl_xor_sync(0xffffffffu, a, 4);
            s[j] = a * 0.08838834764831845f + ((kb + j > gq) ? -1.0e9f : 0.0f);
        }
        float tmax = s[0];
        #pragma unroll
        for (int j = 1; j < 32; j++) tmax = fmaxf(tmax, s[j]);
        float mnew = fmaxf(mrun, tmax);
        float corr = expf(mrun - mnew);      // expf(-inf)=0 handles first tile
        float ps = 0.f;
        #pragma unroll
        for (int j = 0; j < 32; j++) { s[j] = expf(s[j] - mnew); ps += s[j]; }
        lrun = lrun * corr + ps;
        #pragma unroll
        for (int i = 0; i < 16; i++) o_r[i] *= corr;
        #pragma unroll
        for (int j = 0; j < 32; j++) {
            float p = s[j];
            const float* vr = Vs + j * 128 + l8 * 16;
            #pragma unroll
            for (int i = 0; i < 16; i++) o_r[i] = fmaf(p, vr[i], o_r[i]);
        }
        mrun = mnew;
    }

    const float inv = 1.f / lrun;
    const int b = bh >> 5, h = bh & 31;
    float* op = g_att + ((size_t)b * T_ + gq) * C_ + h * D_ + l8 * 16;
    #pragma unroll
    for (int i = 0; i < 16; i++) op[i] = o_r[i] * inv;
}

// ---------------------------------------------------------------------------
// Launch: rope table -> fused QKV (z=0..2) -> attention -> output projection.
// All async on default stream; graph-capturable; no allocations.
// ---------------------------------------------------------------------------
extern "C" void kernel_launch(void* const* d_in, const int* in_sizes, int n_in,
                              void* d_out, int out_size) {
    const float* X  = (const float*)d_in[0];
    const float* Wq = (const float*)d_in[1];
    const float* Wk = (const float*)d_in[2];
    const float* Wv = (const float*)d_in[3];
    const float* Wo = (const float*)d_in[4];
    float* out = (float*)d_out;

    rope_kernel<<<(T_ * 64 + 255) / 256, 256>>>();
    gemm_tf32<0><<<dim3(M_ / BM, N_ / BN, 3), 256>>>(X, Wq, Wk, Wv, nullptr);
    attn_kernel<<<dim3(T_ / 16, B_ * H_), 128>>>();
    gemm_tf32<1><<<dim3(M_ / BM, N_ / BN, 1), 256>>>(nullptr, Wo, nullptr, nullptr, out);
}

// round 3
// speedup vs baseline: 9.4406x; 9.4406x over previous
#include <cuda_runtime.h>
#include <cuda_fp16.h>
#include <cstdint>
#include <math.h>

#define B_ 2
#define T_ 2048
#define C_ 4096
#define H_ 32
#define D_ 128
#define M_ (B_*T_)
#define NELEM 16777216   /* 4096*4096 */

// ---------------- scratch (device globals: allocation-guard safe) -----------
__device__ __half g_xh[NELEM];               // X fp16
__device__ __half g_wh[4*(size_t)NELEM];     // Wq,Wk,Wv,Wo transposed -> [N,K] fp16
__device__ __half g_qh[NELEM];               // q [b,h,t,d] fp16 (rope applied)
__device__ __half g_kh[NELEM];               // k [b,h,t,d] fp16 (rope applied)
__device__ __half g_vh[NELEM];               // v [b,h,t,d] fp16
__device__ __half g_ah[NELEM];               // attention out [b*t, h*D+d] fp16
__device__ float  g_rope[T_*64];

// ---------------- PTX helpers ------------------------------------------------
__device__ __forceinline__ uint32_t smem_u32(const void* p) {
    uint32_t a;
    asm("{ .reg .u64 t; cvta.to.shared.u64 t, %1; cvt.u32.u64 %0, t; }" : "=r"(a) : "l"(p));
    return a;
}
#define CP_ASYNC(dst, src) \
    asm volatile("cp.async.cg.shared.global [%0], [%1], 16;" :: "r"(dst), "l"(src) : "memory")
#define CP_COMMIT() asm volatile("cp.async.commit_group;" ::: "memory")
#define CP_WAIT(n)  asm volatile("cp.async.wait_group %0;" :: "n"(n) : "memory")

#define LDSM4(r0, r1, r2, r3, a) \
    asm volatile("ldmatrix.sync.aligned.m8n8.x4.shared.b16 {%0,%1,%2,%3}, [%4];" \
        : "=r"(r0), "=r"(r1), "=r"(r2), "=r"(r3) : "r"(a))
#define LDSM4T(r0, r1, r2, r3, a) \
    asm volatile("ldmatrix.sync.aligned.m8n8.x4.trans.shared.b16 {%0,%1,%2,%3}, [%4];" \
        : "=r"(r0), "=r"(r1), "=r"(r2), "=r"(r3) : "r"(a))

__device__ __forceinline__ void mma16816(float* d, const uint32_t* a, const uint32_t* b) {
    asm volatile(
        "mma.sync.aligned.m16n8k16.row.col.f32.f16.f16.f32 "
        "{%0,%1,%2,%3}, {%4,%5,%6,%7}, {%8,%9}, {%0,%1,%2,%3};\n"
        : "+f"(d[0]), "+f"(d[1]), "+f"(d[2]), "+f"(d[3])
        : "r"(a[0]), "r"(a[1]), "r"(a[2]), "r"(a[3]), "r"(b[0]), "r"(b[1]));
}

// ---------------- pre-pass kernels -------------------------------------------
__global__ void rope_kernel() {
    int i = blockIdx.x * blockDim.x + threadIdx.x;
    if (i >= T_ * 64) return;
    int t = i >> 6, j = i & 63;
    float f = 1.0f / powf(10000.0f, (float)(2 * j) * (1.0f / 128.0f));
    float m = (float)t * f;
    g_rope[i] = cosf(m) + sinf(m);
}
__global__ void xconv_kernel(const float* __restrict__ X) {
    int i = blockIdx.x * blockDim.x + threadIdx.x;
    g_xh[i] = __float2half_rn(X[i]);
}
// g_wh[z][n*4096+k] = fp16(W[k*4096+n])
__global__ void wtrans_kernel(const float* __restrict__ W0, const float* __restrict__ W1,
                              const float* __restrict__ W2, const float* __restrict__ W3) {
    __shared__ float tb[32][33];
    int zz = blockIdx.z;
    const float* W = (zz == 0) ? W0 : (zz == 1) ? W1 : (zz == 2) ? W2 : W3;
    __half* Wt = g_wh + (size_t)zz * NELEM;
    int n0 = blockIdx.x * 32, k0 = blockIdx.y * 32;
    int tx = threadIdx.x, ty = threadIdx.y;
    #pragma unroll
    for (int i = ty; i < 32; i += 8)
        tb[i][tx] = W[(size_t)(k0 + i) * C_ + n0 + tx];
    __syncthreads();
    #pragma unroll
    for (int i = ty; i < 32; i += 8)
        Wt[(size_t)(n0 + i) * C_ + k0 + tx] = __float2half_rn(tb[tx][i]);
}

// ---------------- fp16 mma GEMM ---------------------------------------------
// C[4096,4096] = A @ W;  A [M,K] fp16 row-major, B = W^T [N,K] fp16 row-major.
// 128x128x64 tiles, 4-stage cp.async, 256 thr (8 warps 2x4, warp tile 64x32).
// MODE 0: A=g_xh, B=g_wh[z];  epilogue rope (z<2) + scatter fp16 q/k/v [b,h,t,d]
// MODE 1: A=g_ah, B=g_wh[3];  fp32 row-major store to Cout.
#define BM 128
#define BN 128
#define BKH 64
#define STAGES 4
#define STG_A (BM*BKH*2)     /* 16384 */
#define STG   (2*STG_A)      /* 32768 */
#define NT    (C_/BKH)       /* 64 */
#define GEMM_SMEM (STAGES*STG)

template<int MODE>
__global__ void __launch_bounds__(256) gemm_h(float* __restrict__ Cout) {
    extern __shared__ char smc[];
    const uint32_t sb = smem_u32(smc);
    const int tid = threadIdx.x;
    const int m0 = blockIdx.x * BM, n0 = blockIdx.y * BN;
    const int z = (MODE == 0) ? blockIdx.z : 3;
    const __half* A  = (MODE == 0) ? g_xh : g_ah;
    const __half* Bm = g_wh + (size_t)z * NELEM;

    auto stage_load = [&](int kt) {
        const uint32_t sa = sb + (kt & 3) * STG;
        const int kc = kt * BKH;
        #pragma unroll
        for (int i = 0; i < 4; i++) {
            int idx = tid + i * 256;
            int r = idx >> 3, c = idx & 7;
            CP_ASYNC(sa + r * 128 + (((uint32_t)(c ^ (r & 7))) << 4),
                     A + (size_t)(m0 + r) * C_ + kc + c * 8);
        }
        #pragma unroll
        for (int i = 0; i < 4; i++) {
            int idx = tid + i * 256;
            int r = idx >> 3, c = idx & 7;
            CP_ASYNC(sa + STG_A + r * 128 + (((uint32_t)(c ^ (r & 7))) << 4),
                     Bm + (size_t)(n0 + r) * C_ + kc + c * 8);
        }
        CP_COMMIT();
    };

    const int wid = tid >> 5, lane = tid & 31;
    const int wm = (wid >> 2) * 64, wn = (wid & 3) * 32;

    float acc[4][4][4];
    #pragma unroll
    for (int i = 0; i < 4; i++)
        #pragma unroll
        for (int j = 0; j < 4; j++)
            #pragma unroll
            for (int k = 0; k < 4; k++) acc[i][j][k] = 0.f;

    stage_load(0); stage_load(1); stage_load(2);

    for (int kt = 0; kt < NT; kt++) {
        CP_WAIT(2);
        __syncthreads();
        if (kt + 3 < NT) stage_load(kt + 3);
        const uint32_t sa = sb + (kt & 3) * STG;
        #pragma unroll
        for (int ks = 0; ks < 4; ks++) {
            uint32_t a[4][4];
            #pragma unroll
            for (int mi = 0; mi < 4; mi++) {
                int r = wm + mi * 16 + (lane & 15);
                int cc = ks * 2 + (lane >> 4);
                LDSM4(a[mi][0], a[mi][1], a[mi][2], a[mi][3],
                      sa + r * 128 + (((uint32_t)(cc ^ (r & 7))) << 4));
            }
            uint32_t b[4][2];
            #pragma unroll
            for (int np = 0; np < 2; np++) {
                int r = wn + np * 16 + (lane & 15);
                int cc = ks * 2 + (lane >> 4);
                uint32_t t0, t1, t2, t3;
                LDSM4(t0, t1, t2, t3,
                      sa + STG_A + r * 128 + (((uint32_t)(cc ^ (r & 7))) << 4));
                b[np*2][0] = t0; b[np*2+1][0] = t1;
                b[np*2][1] = t2; b[np*2+1][1] = t3;
            }
            #pragma unroll
            for (int mi = 0; mi < 4; mi++)
                #pragma unroll
                for (int ni = 0; ni < 4; ni++)
                    mma16816(acc[mi][ni], a[mi], b[ni]);
        }
    }

    // epilogue
    #pragma unroll
    for (int mi = 0; mi < 4; mi++) {
        #pragma unroll
        for (int ni = 0; ni < 4; ni++) {
            #pragma unroll
            for (int h2 = 0; h2 < 2; h2++) {
                int row = m0 + wm + mi * 16 + (lane >> 2) + h2 * 8;
                int col = n0 + wn + ni * 8 + (lane & 3) * 2;
                float v0 = acc[mi][ni][h2 * 2], v1 = acc[mi][ni][h2 * 2 + 1];
                if (MODE == 0) {
                    int b = row >> 11, t = row & (T_ - 1);
                    int h = col >> 7,  d = col & (D_ - 1);
                    if (z < 2) {
                        v0 *= g_rope[t * 64 + (d & 63)];
                        v1 *= g_rope[t * 64 + ((d + 1) & 63)];
                    }
                    __half* dst = (z == 0) ? g_qh : (z == 1) ? g_kh : g_vh;
                    *(__half2*)(dst + (size_t)((b * H_ + h) * T_ + t) * D_ + d) =
                        __floats2half2_rn(v0, v1);
                } else {
                    *(float2*)(Cout + (size_t)row * C_ + col) = make_float2(v0, v1);
                }
            }
        }
    }
}

// ---------------- fp16 mma flash attention ----------------------------------
// CTA: 128 thr (4 warps), q tile 64 rows, kv tiles 64 keys. grid (T/64, B*H).
// S = Q K^T via mma (Q frags resident), online softmax, P fp16 -> smem,
// O += P V via mma with ldmatrix.trans on V. Output fp16 to g_ah [b*t, h*D+d].
#define ROWB 272     /* 136 halves per Q/K/V smem row */
#define PROWB 144    /* 72 halves per P smem row */
#define ATT_SMEM (3*64*ROWB)   /* 52224 */

__global__ void __launch_bounds__(128) attn_h() {
    extern __shared__ char smc[];
    const uint32_t sb = smem_u32(smc);
    const uint32_t sQ = sb, sK = sb + 64 * ROWB, sV = sb + 2 * 64 * ROWB;
    const int tid = threadIdx.x, w = tid >> 5, lane = tid & 31;
    const int bh = blockIdx.y, q0 = blockIdx.x * 64;
    const __half* Qg = g_qh + (size_t)bh * T_ * D_;
    const __half* Kg = g_kh + (size_t)bh * T_ * D_;
    const __half* Vg = g_vh + (size_t)bh * T_ * D_;

    // stage Q tile
    #pragma unroll
    for (int i = 0; i < 8; i++) {
        int idx = tid + i * 128;
        int r = idx >> 4, c = idx & 15;
        CP_ASYNC(sQ + r * ROWB + c * 16, Qg + (size_t)(q0 + r) * D_ + c * 8);
    }
    CP_COMMIT(); CP_WAIT(0); __syncthreads();

    uint32_t qf[8][4];
    #pragma unroll
    for (int ks = 0; ks < 8; ks++) {
        int r = w * 16 + (lane & 15), cc = ks * 2 + (lane >> 4);
        LDSM4(qf[ks][0], qf[ks][1], qf[ks][2], qf[ks][3], sQ + r * ROWB + cc * 16);
    }
    __syncthreads();   // Q smem region now reused for P

    float oacc[16][4];
    #pragma unroll
    for (int i = 0; i < 16; i++)
        #pragma unroll
        for (int j = 0; j < 4; j++) oacc[i][j] = 0.f;
    float mrow[2] = {-INFINITY, -INFINITY}, lrow[2] = {0.f, 0.f};
    const float scale = 0.08838834764831845f;
    const int r0 = lane >> 2, c0 = (lane & 3) * 2;

    for (int t0 = 0; t0 <= q0; t0 += 64) {
        __syncthreads();   // all warps done with previous K/V
        #pragma unroll
        for (int i = 0; i < 8; i++) {
            int idx = tid + i * 128;
            int r = idx >> 4, c = idx & 15;
            CP_ASYNC(sK + r * ROWB + c * 16, Kg + (size_t)(t0 + r) * D_ + c * 8);
        }
        #pragma unroll
        for (int i = 0; i < 8; i++) {
            int idx = tid + i * 128;
            int r = idx >> 4, c = idx & 15;
            CP_ASYNC(sV + r * ROWB + c * 16, Vg + (size_t)(t0 + r) * D_ + c * 8);
        }
        CP_COMMIT(); CP_WAIT(0); __syncthreads();

        // S = Q K^T  (64x64 per CTA, 16x64 per warp)
        float sacc[8][4];
        #pragma unroll
        for (int f = 0; f < 8; f++)
            #pragma unroll
            for (int j = 0; j < 4; j++) sacc[f][j] = 0.f;
        #pragma unroll
        for (int ks = 0; ks < 8; ks++) {
            uint32_t b[8][2];
            #pragma unroll
            for (int np = 0; np < 4; np++) {
                int r = np * 16 + (lane & 15), cc = ks * 2 + (lane >> 4);
                uint32_t t0_, t1_, t2_, t3_;
                LDSM4(t0_, t1_, t2_, t3_, sK + r * ROWB + cc * 16);
                b[np*2][0] = t0_; b[np*2+1][0] = t1_;
                b[np*2][1] = t2_; b[np*2+1][1] = t3_;
            }
            #pragma unroll
            for (int f = 0; f < 8; f++) mma16816(sacc[f], qf[ks], b[f]);
        }

        // online softmax
        const bool diag = (t0 == q0);
        float mt[2] = {-INFINITY, -INFINITY};
        #pragma unroll
        for (int f = 0; f < 8; f++) {
            #pragma unroll
            for (int j = 0; j < 4; j++) {
                float v = sacc[f][j] * scale;
                if (diag) {
                    int col = f * 8 + c0 + (j & 1);
                    int rr  = w * 16 + r0 + (j >> 1) * 8;
                    if (col > rr) v = -1e30f;
                }
                sacc[f][j] = v;
                mt[j >> 1] = fmaxf(mt[j >> 1], v);
            }
        }
        float corr[2], rs[2] = {0.f, 0.f};
        #pragma unroll
        for (int h2 = 0; h2 < 2; h2++) {
            mt[h2] = fmaxf(mt[h2], __shfl_xor_sync(0xffffffffu, mt[h2], 1));
            mt[h2] = fmaxf(mt[h2], __shfl_xor_sync(0xffffffffu, mt[h2], 2));
            float mn = fmaxf(mrow[h2], mt[h2]);
            corr[h2] = __expf(mrow[h2] - mn);
            mrow[h2] = mn;
        }
        #pragma unroll
        for (int f = 0; f < 8; f++) {
            #pragma unroll
            for (int j = 0; j < 4; j++) {
                float p = __expf(sacc[f][j] - mrow[j >> 1]);
                sacc[f][j] = p;
                rs[j >> 1] += p;
            }
        }
        #pragma unroll
        for (int h2 = 0; h2 < 2; h2++) {
            rs[h2] += __shfl_xor_sync(0xffffffffu, rs[h2], 1);
            rs[h2] += __shfl_xor_sync(0xffffffffu, rs[h2], 2);
            lrow[h2] = lrow[h2] * corr[h2] + rs[h2];
        }
        #pragma unroll
        for (int f = 0; f < 16; f++)
            #pragma unroll
            for (int j = 0; j < 4; j++) oacc[f][j] *= corr[j >> 1];

        // P -> smem fp16 (per-warp region overlaying Q)
        __syncwarp();
        #pragma unroll
        for (int f = 0; f < 8; f++) {
            #pragma unroll
            for (int h2 = 0; h2 < 2; h2++) {
                uint32_t off = (uint32_t)((w * 16 + r0 + h2 * 8) * PROWB + (f * 8 + c0) * 2);
                *(__half2*)(smc + off) = __floats2half2_rn(sacc[f][h2*2], sacc[f][h2*2+1]);
            }
        }
        __syncwarp();

        // O += P V
        #pragma unroll
        for (int ks = 0; ks < 4; ks++) {
            uint32_t a[4];
            {
                int r = w * 16 + (lane & 15), cc = ks * 2 + (lane >> 4);
                LDSM4(a[0], a[1], a[2], a[3], sQ + (uint32_t)(r * PROWB + cc * 16));
            }
            #pragma unroll
            for (int dp = 0; dp < 8; dp++) {
                int vr = ks * 16 + (lane & 15), vc = dp * 2 + (lane >> 4);
                uint32_t t0_, t1_, t2_, t3_;
                LDSM4T(t0_, t1_, t2_, t3_, sV + vr * ROWB + vc * 16);
                uint32_t b0[2] = {t0_, t1_}, b1[2] = {t2_, t3_};
                mma16816(oacc[dp*2],   a, b0);
                mma16816(oacc[dp*2+1], a, b1);
            }
        }
    }

    // epilogue
    float inv[2] = {1.f / lrow[0], 1.f / lrow[1]};
    const int bq = bh >> 5, hh = bh & 31;
    #pragma unroll
    for (int dp = 0; dp < 16; dp++) {
        #pragma unroll
        for (int h2 = 0; h2 < 2; h2++) {
            int row = q0 + w * 16 + r0 + h2 * 8;
            int col = hh * D_ + dp * 8 + c0;
            *(__half2*)(g_ah + (size_t)(bq * T_ + row) * C_ + col) =
                __floats2half2_rn(oacc[dp][h2*2] * inv[h2], oacc[dp][h2*2+1] * inv[h2]);
        }
    }
}

// ---------------- launch -----------------------------------------------------
extern "C" void kernel_launch(void* const* d_in, const int* in_sizes, int n_in,
                              void* d_out, int out_size) {
    const float* X  = (const float*)d_in[0];
    const float* Wq = (const float*)d_in[1];
    const float* Wk = (const float*)d_in[2];
    const float* Wv = (const float*)d_in[3];
    const float* Wo = (const float*)d_in[4];
    float* out = (float*)d_out;

    cudaFuncSetAttribute(gemm_h<0>, cudaFuncAttributeMaxDynamicSharedMemorySize, GEMM_SMEM);
    cudaFuncSetAttribute(gemm_h<1>, cudaFuncAttributeMaxDynamicSharedMemorySize, GEMM_SMEM);
    cudaFuncSetAttribute(attn_h,    cudaFuncAttributeMaxDynamicSharedMemorySize, ATT_SMEM);

    rope_kernel<<<(T_ * 64 + 255) / 256, 256>>>();
    xconv_kernel<<<NELEM / 256, 256>>>(X);
    wtrans_kernel<<<dim3(128, 128, 4), dim3(32, 8)>>>(Wq, Wk, Wv, Wo);

    gemm_h<0><<<dim3(M_ / BM, C_ / BN, 3), 256, GEMM_SMEM>>>(nullptr);
    attn_h<<<dim3(T_ / 64, B_ * H_), 128, ATT_SMEM>>>();
    gemm_h<1><<<dim3(M_ / BM, C_ / BN, 1), 256, GEMM_SMEM>>>(out);
}

// round 5
// speedup vs baseline: 13.3028x; 1.4091x over previous
#include <cuda_runtime.h>
#include <cuda_fp16.h>
#include <cstdint>
#include <math.h>

#define B_ 2
#define T_ 2048
#define C_ 4096
#define H_ 32
#define D_ 128
#define M_ (B_*T_)
#define NELEM 16777216   /* 4096*4096 */

// ---------------- scratch (device globals: allocation-guard safe) -----------
__device__ __half g_xh[NELEM];               // X fp16 [M,K]
__device__ __half g_wh[4*(size_t)NELEM];     // Wq,Wk,Wv,Wo fp16, ORIGINAL [K,N] layout
__device__ __half g_qh[NELEM];               // q [b,h,t,d] fp16 (rope applied)
__device__ __half g_kh[NELEM];               // k [b,h,t,d] fp16 (rope applied)
__device__ __half g_vh[NELEM];               // v [b,h,t,d] fp16
__device__ __half g_ah[NELEM];               // attention out [b*t, h*D+d] fp16
__device__ float  g_rope[T_*64];

// ---------------- PTX helpers ------------------------------------------------
__device__ __forceinline__ uint32_t smem_u32(const void* p) {
    uint32_t a;
    asm("{ .reg .u64 t; cvta.to.shared.u64 t, %1; cvt.u32.u64 %0, t; }" : "=r"(a) : "l"(p));
    return a;
}
#define CP_ASYNC(dst, src) \
    asm volatile("cp.async.cg.shared.global [%0], [%1], 16;" :: "r"(dst), "l"(src) : "memory")
#define CP_COMMIT() asm volatile("cp.async.commit_group;" ::: "memory")
#define CP_WAIT(n)  asm volatile("cp.async.wait_group %0;" :: "n"(n) : "memory")

#define LDSM4(r0, r1, r2, r3, a) \
    asm volatile("ldmatrix.sync.aligned.m8n8.x4.shared.b16 {%0,%1,%2,%3}, [%4];" \
        : "=r"(r0), "=r"(r1), "=r"(r2), "=r"(r3) : "r"(a))
#define LDSM4T(r0, r1, r2, r3, a) \
    asm volatile("ldmatrix.sync.aligned.m8n8.x4.trans.shared.b16 {%0,%1,%2,%3}, [%4];" \
        : "=r"(r0), "=r"(r1), "=r"(r2), "=r"(r3) : "r"(a))

__device__ __forceinline__ void mma16816(float* d, const uint32_t* a, const uint32_t* b) {
    asm volatile(
        "mma.sync.aligned.m16n8k16.row.col.f32.f16.f16.f32 "
        "{%0,%1,%2,%3}, {%4,%5,%6,%7}, {%8,%9}, {%0,%1,%2,%3};\n"
        : "+f"(d[0]), "+f"(d[1]), "+f"(d[2]), "+f"(d[3])
        : "r"(a[0]), "r"(a[1]), "r"(a[2]), "r"(a[3]), "r"(b[0]), "r"(b[1]));
}

// ---------------- pre-pass kernels -------------------------------------------
__global__ void rope_kernel() {
    int i = blockIdx.x * blockDim.x + threadIdx.x;
    if (i >= T_ * 64) return;
    int t = i >> 6, j = i & 63;
    float f = 1.0f / powf(10000.0f, (float)(2 * j) * (1.0f / 128.0f));
    float m = (float)t * f;
    g_rope[i] = cosf(m) + sinf(m);
}
// vectorized fp32 -> fp16 streaming convert (4 elems/thread)
__global__ void xconv_kernel(const float* __restrict__ X) {
    int i = blockIdx.x * blockDim.x + threadIdx.x;
    float4 v = *(const float4*)(X + (size_t)i * 4);
    __half2 h0 = __floats2half2_rn(v.x, v.y);
    __half2 h1 = __floats2half2_rn(v.z, v.w);
    *(__half2*)(g_xh + (size_t)i * 4)     = h0;
    *(__half2*)(g_xh + (size_t)i * 4 + 2) = h1;
}
__global__ void wconv_kernel(const float* __restrict__ W0, const float* __restrict__ W1,
                             const float* __restrict__ W2, const float* __restrict__ W3) {
    int z = blockIdx.y;
    const float* W = (z == 0) ? W0 : (z == 1) ? W1 : (z == 2) ? W2 : W3;
    __half* Wh = g_wh + (size_t)z * NELEM;
    int i = blockIdx.x * blockDim.x + threadIdx.x;
    float4 v = *(const float4*)(W + (size_t)i * 4);
    *(__half2*)(Wh + (size_t)i * 4)     = __floats2half2_rn(v.x, v.y);
    *(__half2*)(Wh + (size_t)i * 4 + 2) = __floats2half2_rn(v.z, v.w);
}

// ---------------- fp16 mma GEMM ---------------------------------------------
// C[4096,4096] = A @ W;  A [M,K] fp16 row-major, W [K,N] fp16 row-major.
// 128x128x64 tiles, 3-stage cp.async (96KB -> 2 CTAs/SM), 256 thr
// (8 warps 2x4, warp tile 64x32). A frags via ldmatrix, B frags via
// ldmatrix.trans on [K,N] tiles (no weight pre-transpose).
// MODE 0: A=g_xh, W=g_wh[z]; epilogue rope (z<2) + scatter fp16 q/k/v [b,h,t,d]
// MODE 1: A=g_ah, W=g_wh[3]; fp32 row-major store to Cout.
#define BM 128
#define BN 128
#define BKH 64
#define STG_A (BM*BKH*2)     /* 16384 */
#define STG   (2*STG_A)      /* 32768: A then B(64 rows x 256B) */
#define NT    (C_/BKH)       /* 64 */
#define GEMM_SMEM (3*STG)    /* 98304 */

template<int MODE>
__global__ void __launch_bounds__(256, 2) gemm_h(float* __restrict__ Cout) {
    extern __shared__ char smc[];
    const uint32_t sb = smem_u32(smc);
    const int tid = threadIdx.x;
    const int m0 = blockIdx.x * BM, n0 = blockIdx.y * BN;
    const int z = (MODE == 0) ? blockIdx.z : 3;
    const __half* A  = (MODE == 0) ? g_xh : g_ah;
    const __half* Wm = g_wh + (size_t)z * NELEM;

    auto stage_load = [&](int kt) {
        const uint32_t sa = sb + (kt % 3) * STG;
        const int kc = kt * BKH;
        #pragma unroll
        for (int i = 0; i < 4; i++) {          // A: 128 rows x 8 chunks of 16B
            int idx = tid + i * 256;
            int r = idx >> 3, c = idx & 7;
            CP_ASYNC(sa + r * 128 + (((uint32_t)(c ^ (r & 7))) << 4),
                     A + (size_t)(m0 + r) * C_ + kc + c * 8);
        }
        #pragma unroll
        for (int i = 0; i < 4; i++) {          // B: 64 rows x 16 chunks of 16B
            int idx = tid + i * 256;
            int r = idx >> 4, c = idx & 15;
            CP_ASYNC(sa + STG_A + r * 256 + (((uint32_t)(c ^ (r & 7))) << 4),
                     Wm + (size_t)(kc + r) * C_ + n0 + c * 8);
        }
        CP_COMMIT();
    };

    const int wid = tid >> 5, lane = tid & 31;
    const int wm = (wid >> 2) * 64, wn = (wid & 3) * 32;

    float acc[4][4][4];
    #pragma unroll
    for (int i = 0; i < 4; i++)
        #pragma unroll
        for (int j = 0; j < 4; j++)
            #pragma unroll
            for (int k = 0; k < 4; k++) acc[i][j][k] = 0.f;

    stage_load(0); stage_load(1);

    for (int kt = 0; kt < NT; kt++) {
        if (kt < NT - 1) { CP_WAIT(1); } else { CP_WAIT(0); }
        __syncthreads();
        if (kt + 2 < NT) stage_load(kt + 2);
        const uint32_t sa = sb + (kt % 3) * STG;
        #pragma unroll
        for (int ks = 0; ks < 4; ks++) {
            uint32_t a[4][4];
            #pragma unroll
            for (int mi = 0; mi < 4; mi++) {
                int r = wm + mi * 16 + (lane & 15);
                int cc = ks * 2 + (lane >> 4);
                LDSM4(a[mi][0], a[mi][1], a[mi][2], a[mi][3],
                      sa + r * 128 + (((uint32_t)(cc ^ (r & 7))) << 4));
            }
            uint32_t b[4][2];
            #pragma unroll
            for (int np = 0; np < 2; np++) {   // trans-load from [K,N] tile
                int r = ks * 16 + (lane & 15);
                int c = (wn >> 3) + np * 2 + (lane >> 4);
                uint32_t t0, t1, t2, t3;
                LDSM4T(t0, t1, t2, t3,
                       sa + STG_A + r * 256 + (((uint32_t)(c ^ (r & 7))) << 4));
                b[np*2][0] = t0; b[np*2][1] = t1;
                b[np*2+1][0] = t2; b[np*2+1][1] = t3;
            }
            #pragma unroll
            for (int mi = 0; mi < 4; mi++)
                #pragma unroll
                for (int ni = 0; ni < 4; ni++)
                    mma16816(acc[mi][ni], a[mi], b[ni]);
        }
    }

    // epilogue
    #pragma unroll
    for (int mi = 0; mi < 4; mi++) {
        #pragma unroll
        for (int ni = 0; ni < 4; ni++) {
            #pragma unroll
            for (int h2 = 0; h2 < 2; h2++) {
                int row = m0 + wm + mi * 16 + (lane >> 2) + h2 * 8;
                int col = n0 + wn + ni * 8 + (lane & 3) * 2;
                float v0 = acc[mi][ni][h2 * 2], v1 = acc[mi][ni][h2 * 2 + 1];
                if (MODE == 0) {
                    int b = row >> 11, t = row & (T_ - 1);
                    int h = col >> 7,  d = col & (D_ - 1);
                    if (z < 2) {
                        v0 *= g_rope[t * 64 + (d & 63)];
                        v1 *= g_rope[t * 64 + ((d + 1) & 63)];
                    }
                    __half* dst = (z == 0) ? g_qh : (z == 1) ? g_kh : g_vh;
                    *(__half2*)(dst + (size_t)((b * H_ + h) * T_ + t) * D_ + d) =
                        __floats2half2_rn(v0, v1);
                } else {
                    *(float2*)(Cout + (size_t)row * C_ + col) = make_float2(v0, v1);
                }
            }
        }
    }
}

// ---------------- fp16 mma flash attention (double-buffered K/V) ------------
// CTA: 128 thr (4 warps), q tile 64 rows, kv tiles 64 keys, 2 K slots + 2 V
// slots. grid (T/64, B*H). Output fp16 -> g_ah [b*t, h*D+d].
#define ROWB 272     /* 136 halves per Q/K/V smem row (16B skew) */
#define PROWB 144    /* 72 halves per P smem row */
#define QSZ (64*ROWB)          /* 17408 */
#define ATT_SMEM (5*QSZ)       /* Q + 2K + 2V = 87040 */

__global__ void __launch_bounds__(128, 2) attn_h() {
    extern __shared__ char smc[];
    const uint32_t sb = smem_u32(smc);
    const uint32_t sQ = sb;
    const int tid = threadIdx.x, w = tid >> 5, lane = tid & 31;
    const int bh = blockIdx.y, q0 = blockIdx.x * 64;
    const __half* Qg = g_qh + (size_t)bh * T_ * D_;
    const __half* Kg = g_kh + (size_t)bh * T_ * D_;
    const __half* Vg = g_vh + (size_t)bh * T_ * D_;

    auto loadKV = [&](int tile, int slot) {
        const uint32_t sK = sb + QSZ + slot * QSZ;
        const uint32_t sV = sb + 3 * QSZ + slot * QSZ;
        const int t0 = tile * 64;
        #pragma unroll
        for (int i = 0; i < 8; i++) {
            int idx = tid + i * 128;
            int r = idx >> 4, c = idx & 15;
            CP_ASYNC(sK + r * ROWB + c * 16, Kg + (size_t)(t0 + r) * D_ + c * 8);
        }
        #pragma unroll
        for (int i = 0; i < 8; i++) {
            int idx = tid + i * 128;
            int r = idx >> 4, c = idx & 15;
            CP_ASYNC(sV + r * ROWB + c * 16, Vg + (size_t)(t0 + r) * D_ + c * 8);
        }
        CP_COMMIT();
    };

    // stage Q (group 0), then KV tile 0 (group 1)
    #pragma unroll
    for (int i = 0; i < 8; i++) {
        int idx = tid + i * 128;
        int r = idx >> 4, c = idx & 15;
        CP_ASYNC(sQ + r * ROWB + c * 16, Qg + (size_t)(q0 + r) * D_ + c * 8);
    }
    CP_COMMIT();
    loadKV(0, 0);
    CP_WAIT(1);                 // Q resident
    __syncthreads();

    uint32_t qf[8][4];
    #pragma unroll
    for (int ks = 0; ks < 8; ks++) {
        int r = w * 16 + (lane & 15), cc = ks * 2 + (lane >> 4);
        LDSM4(qf[ks][0], qf[ks][1], qf[ks][2], qf[ks][3], sQ + r * ROWB + cc * 16);
    }

    float oacc[16][4];
    #pragma unroll
    for (int i = 0; i < 16; i++)
        #pragma unroll
        for (int j = 0; j < 4; j++) oacc[i][j] = 0.f;
    float mrow[2] = {-INFINITY, -INFINITY}, lrow[2] = {0.f, 0.f};
    const float scale = 0.08838834764831845f;
    const int r0 = lane >> 2, c0 = (lane & 3) * 2;
    const int ntiles = q0 / 64 + 1;

    for (int it = 0; it < ntiles; it++) {
        __syncthreads();        // prev compute done (slot (it+1)&1 free; Q frags read)
        if (it + 1 < ntiles) { loadKV(it + 1, (it + 1) & 1); CP_WAIT(1); }
        else                 { CP_WAIT(0); }
        __syncthreads();        // tile it resident for all threads

        const uint32_t sK = sb + QSZ + (it & 1) * QSZ;
        const uint32_t sV = sb + 3 * QSZ + (it & 1) * QSZ;

        // S = Q K^T  (16x64 per warp)
        float sacc[8][4];
        #pragma unroll
        for (int f = 0; f < 8; f++)
            #pragma unroll
            for (int j = 0; j < 4; j++) sacc[f][j] = 0.f;
        #pragma unroll
        for (int ks = 0; ks < 8; ks++) {
            uint32_t b[8][2];
            #pragma unroll
            for (int np = 0; np < 4; np++) {
                int r = np * 16 + (lane & 15), cc = ks * 2 + (lane >> 4);
                uint32_t t0_, t1_, t2_, t3_;
                LDSM4(t0_, t1_, t2_, t3_, sK + r * ROWB + cc * 16);
                b[np*2][0] = t0_; b[np*2+1][0] = t1_;
                b[np*2][1] = t2_; b[np*2+1][1] = t3_;
            }
            #pragma unroll
            for (int f = 0; f < 8; f++) mma16816(sacc[f], qf[ks], b[f]);
        }

        // online softmax
        const bool diag = (it == ntiles - 1);
        float mt[2] = {-INFINITY, -INFINITY};
        #pragma unroll
        for (int f = 0; f < 8; f++) {
            #pragma unroll
            for (int j = 0; j < 4; j++) {
                float v = sacc[f][j] * scale;
                if (diag) {
                    int col = f * 8 + c0 + (j & 1);
                    int rr  = w * 16 + r0 + (j >> 1) * 8;
                    if (col > rr) v = -1e30f;
                }
                sacc[f][j] = v;
                mt[j >> 1] = fmaxf(mt[j >> 1], v);
            }
        }
        float corr[2], rs[2] = {0.f, 0.f};
        #pragma unroll
        for (int h2 = 0; h2 < 2; h2++) {
            mt[h2] = fmaxf(mt[h2], __shfl_xor_sync(0xffffffffu, mt[h2], 1));
            mt[h2] = fmaxf(mt[h2], __shfl_xor_sync(0xffffffffu, mt[h2], 2));
            float mn = fmaxf(mrow[h2], mt[h2]);
            corr[h2] = __expf(mrow[h2] - mn);
            mrow[h2] = mn;
        }
        #pragma unroll
        for (int f = 0; f < 8; f++) {
            #pragma unroll
            for (int j = 0; j < 4; j++) {
                float p = __expf(sacc[f][j] - mrow[j >> 1]);
                sacc[f][j] = p;
                rs[j >> 1] += p;
            }
        }
        #pragma unroll
        for (int h2 = 0; h2 < 2; h2++) {
            rs[h2] += __shfl_xor_sync(0xffffffffu, rs[h2], 1);
            rs[h2] += __shfl_xor_sync(0xffffffffu, rs[h2], 2);
            lrow[h2] = lrow[h2] * corr[h2] + rs[h2];
        }
        #pragma unroll
        for (int f = 0; f < 16; f++)
            #pragma unroll
            for (int j = 0; j < 4; j++) oacc[f][j] *= corr[j >> 1];

        // P -> smem fp16 (per-warp private rows overlaying Q)
        __syncwarp();
        #pragma unroll
        for (int f = 0; f < 8; f++) {
            #pragma unroll
            for (int h2 = 0; h2 < 2; h2++) {
                uint32_t off = (uint32_t)((w * 16 + r0 + h2 * 8) * PROWB + (f * 8 + c0) * 2);
                *(__half2*)(smc + off) = __floats2half2_rn(sacc[f][h2*2], sacc[f][h2*2+1]);
            }
        }
        __syncwarp();

        // O += P V
        #pragma unroll
        for (int ks = 0; ks < 4; ks++) {
            uint32_t a[4];
            {
                int r = w * 16 + (lane & 15), cc = ks * 2 + (lane >> 4);
                LDSM4(a[0], a[1], a[2], a[3], sQ + (uint32_t)(r * PROWB + cc * 16));
            }
            #pragma unroll
            for (int dp = 0; dp < 8; dp++) {
                int vr = ks * 16 + (lane & 15), vc = dp * 2 + (lane >> 4);
                uint32_t t0_, t1_, t2_, t3_;
                LDSM4T(t0_, t1_, t2_, t3_, sV + vr * ROWB + vc * 16);
                uint32_t b0[2] = {t0_, t1_}, b1[2] = {t2_, t3_};
                mma16816(oacc[dp*2],   a, b0);
                mma16816(oacc[dp*2+1], a, b1);
            }
        }
    }

    // epilogue
    float inv[2] = {1.f / lrow[0], 1.f / lrow[1]};
    const int bq = bh >> 5, hh = bh & 31;
    #pragma unroll
    for (int dp = 0; dp < 16; dp++) {
        #pragma unroll
        for (int h2 = 0; h2 < 2; h2++) {
            int row = q0 + w * 16 + r0 + h2 * 8;
            int col = hh * D_ + dp * 8 + c0;
            *(__half2*)(g_ah + (size_t)(bq * T_ + row) * C_ + col) =
                __floats2half2_rn(oacc[dp][h2*2] * inv[h2], oacc[dp][h2*2+1] * inv[h2]);
        }
    }
}

// ---------------- launch -----------------------------------------------------
extern "C" void kernel_launch(void* const* d_in, const int* in_sizes, int n_in,
                              void* d_out, int out_size) {
    const float* X  = (const float*)d_in[0];
    const float* Wq = (const float*)d_in[1];
    const float* Wk = (const float*)d_in[2];
    const float* Wv = (const float*)d_in[3];
    const float* Wo = (const float*)d_in[4];
    float* out = (float*)d_out;

    cudaFuncSetAttribute(gemm_h<0>, cudaFuncAttributeMaxDynamicSharedMemorySize, GEMM_SMEM);
    cudaFuncSetAttribute(gemm_h<1>, cudaFuncAttributeMaxDynamicSharedMemorySize, GEMM_SMEM);
    cudaFuncSetAttribute(attn_h,    cudaFuncAttributeMaxDynamicSharedMemorySize, ATT_SMEM);

    rope_kernel<<<(T_ * 64 + 255) / 256, 256>>>();
    xconv_kernel<<<NELEM / 1024, 256>>>(X);
    wconv_kernel<<<dim3(NELEM / 1024, 4), 256>>>(Wq, Wk, Wv, Wo);

    gemm_h<0><<<dim3(M_ / BM, C_ / BN, 3), 256, GEMM_SMEM>>>(nullptr);
    attn_h<<<dim3(T_ / 64, B_ * H_), 128, ATT_SMEM>>>();
    gemm_h<1><<<dim3(M_ / BM, C_ / BN, 1), 256, GEMM_SMEM>>>(out);
}